// round 13
// baseline (speedup 1.0000x reference)
#include <cuda_runtime.h>
#include <cuda_fp16.h>
#include <cstdint>

// ---------------- problem constants ----------------
constexpr int Bn = 128;   // batch (GEMM M)
constexpr int In = 1024;  // input features
constexpr int Hn = 4096;  // hidden
constexpr int On = 512;   // output
constexpr int Tn = 100;   // timesteps
constexpr int S1 = 4;     // k-splits GEMM1 (base K 1024 -> 256/CTA)
constexpr int S2 = 32;    // k-splits GEMM2 (base K 4096 -> 128/CTA)
constexpr int NB1 = 8;    // 32-col chunks per CTA, GEMM1
constexpr int NB2 = 2;    // 64-col chunks per CTA, GEMM2
constexpr int NT1 = 128;  // gemm1 tiles per step (32n x 4z, full-M tiles)
constexpr int K1A = 2 * In;   // g_a1 row: [A0 | A1]
constexpr int K1W = 2 * In;   // g_w1 row: [W0 | W1s]
constexpr int K2W = 2 * Hn;   // g_w2 row: [W0 | W1s]

constexpr int TILE_W = 16384;  // 128x64 fp16 tile (gemm2)
constexpr int TILE_N = 8192;   // 128x32 fp16 tile (gemm1, 64B rows)
constexpr int STG1   = 4 * TILE_N;               // 32KB: A0,A1,W0,W1s (32 cols)
constexpr int SMEM_C = 6 * TILE_W;               // 96KB (gemm2 path; gemm1 uses 2*STG1=64KB)

constexpr size_t P1SZ = (size_t)S1 * Bn * Hn;
constexpr size_t P2SZ = (size_t)S2 * Bn * On;

constexpr float VDEC = 0.5f;
constexpr float VTH  = 0.3f;
constexpr float GW   = 0.3f;

// ---------------- device scratch ----------------
__device__ __half g_a1[(size_t)Tn * Bn * K1A];  // [T][B][2048] 52.4MB
__device__ __half g_w1[(size_t)Hn * K1W];       // [H][2048] 16.8MB
__device__ __half g_w2[(size_t)On * K2W];       // [O][8192] 8.4MB
__device__ float    g_hv[Bn * Hn];
__device__ float    g_ov[Bn * On];
__device__ float    g_p1[2 * P1SZ];             // double-buffered by t&1
__device__ float    g_p2[2 * P2SZ];             // double-buffered by t&1
__device__ unsigned g_maxh[Tn];
__device__ unsigned g_maxo[Tn];
__device__ int      g_cc[Tn];                   // per-step gemm2 arrival counters

// ---------------- helpers ----------------
__device__ __forceinline__ unsigned enc_f(float x) {
    unsigned u = __float_as_uint(x);
    return (u & 0x80000000u) ? ~u : (u | 0x80000000u);
}
__device__ __forceinline__ float dec_f(unsigned k) {
    unsigned u = (k & 0x80000000u) ? (k & 0x7FFFFFFFu) : ~k;
    return __uint_as_float(u);
}
__device__ __forceinline__ float block_max256(float v) {
    #pragma unroll
    for (int o = 16; o > 0; o >>= 1)
        v = fmaxf(v, __shfl_xor_sync(0xffffffffu, v, o));
    __shared__ float red[8];
    int w = threadIdx.x >> 5;
    if ((threadIdx.x & 31) == 0) red[w] = v;
    __syncthreads();
    if (threadIdx.x == 0) {
        #pragma unroll
        for (int i = 1; i < 8; i++) v = fmaxf(v, red[i]);
    }
    return v;
}
__device__ __forceinline__ uint32_t smem_to_u32(const void* p) {
    uint32_t a;
    asm("{ .reg .u64 t; cvta.to.shared.u64 t, %1; cvt.u32.u64 %0, t; }" : "=r"(a) : "l"(p));
    return a;
}

#define LDSM_X4(r0, r1, r2, r3, addr) \
    asm volatile("ldmatrix.sync.aligned.m8n8.x4.shared.b16 {%0,%1,%2,%3}, [%4];" \
        : "=r"(r0), "=r"(r1), "=r"(r2), "=r"(r3) : "r"(addr))

#define MMA16816(d, a, b0, b1) \
    asm volatile("mma.sync.aligned.m16n8k16.row.col.f32.f16.f16.f32 " \
        "{%0,%1,%2,%3}, {%4,%5,%6,%7}, {%8,%9}, {%0,%1,%2,%3};" \
        : "+f"((d)[0]), "+f"((d)[1]), "+f"((d)[2]), "+f"((d)[3]) \
        : "r"((a)[0]), "r"((a)[1]), "r"((a)[2]), "r"((a)[3]), "r"(b0), "r"(b1))

#define HMUL2(o, x, y) asm("mul.f16x2 %0, %1, %2;" : "=r"(o) : "r"(x), "r"(y))

#define CP_ASYNC16(sdst, gsrc) \
    asm volatile("cp.async.cg.shared.global [%0], [%1], 16;" :: "r"(sdst), "l"(gsrc) : "memory")
#define CP_COMMIT() asm volatile("cp.async.commit_group;" ::: "memory")
#define CP_WAIT(n)  asm volatile("cp.async.wait_group %0;" :: "n"(n) : "memory")

// 128 rows x 64 fp16 tile (128B rows, SW128 swizzle) — gemm2
__device__ __forceinline__ void cp_tile128(uint32_t sdst, const __half* __restrict__ src, int ld) {
    int tid = threadIdx.x;
    #pragma unroll
    for (int p = 0; p < 4; p++) {
        int id  = p * 256 + tid;
        int row = id >> 3, g = id & 7;
        uint32_t off = (uint32_t)(row * 128 + g * 16);
        off ^= (off >> 3) & 0x70u;
        CP_ASYNC16(sdst + off, src + (size_t)row * ld + g * 8);
    }
}
// 128 rows x 32 fp16 tile (64B rows, SW64 swizzle) — gemm1
__device__ __forceinline__ void cp_tile32(uint32_t sdst, const __half* __restrict__ src, int ld) {
    int tid = threadIdx.x;
    #pragma unroll
    for (int p = 0; p < 2; p++) {
        int id  = p * 256 + tid;   // 512 16B granules
        int row = id >> 2, g = id & 3;
        uint32_t off = (uint32_t)(row * 64 + g * 16);
        off ^= (off >> 3) & 0x30u;
        CP_ASYNC16(sdst + off, src + (size_t)row * ld + g * 8);
    }
}

// ================= GEMM1 body: 128x128 output tile, 32-col chunks =================
// tile id in [0,128): nt = id&31, z = id>>5. stage tiles (8KB ea): 0=A0,1=A1,2=W0,3=W1s
__device__ __forceinline__ void gemm1_body(int t, int bid_g, uint32_t sbase) {
    const int tid  = threadIdx.x;
    const int wid  = tid >> 5, lane = tid & 31;
    const int wm   = wid & 1, wn = wid >> 1;      // 2m x 4n, warp tile 64x32
    const int nt   = bid_g & 31;
    const int z    = bid_g >> 5;                  // 0..3
    const int n0   = nt * 128;
    const int kbase = z * 256;

    const __half* Abase = g_a1 + (size_t)t * Bn * K1A;

    auto issue = [&](int c) {
        if (c < NB1) {
            uint32_t st = sbase + (uint32_t)(c & 1) * (uint32_t)STG1;
            int kk = kbase + c * 32;
            cp_tile32(st,              Abase + 0 * In + kk, K1A);
            cp_tile32(st + TILE_N,     Abase + 1 * In + kk, K1A);
            cp_tile32(st + 2 * TILE_N, g_w1 + (size_t)n0 * K1W + 0 * In + kk, K1W);
            cp_tile32(st + 3 * TILE_N, g_w1 + (size_t)n0 * K1W + 1 * In + kk, K1W);
        }
        CP_COMMIT();
    };

    // ldmatrix addressing (64B rows, SW64 swizzle)
    const int grp = lane >> 3, lrow = lane & 7;
    const int a_row = lrow + ((grp & 1) << 3);
    const uint32_t a_kb = (uint32_t)((grp >> 1) << 4);
    const int b_row = lrow + ((grp >> 1) << 3);
    const uint32_t b_kb = (uint32_t)((grp & 1) << 4);
    uint32_t aRB[4], aXR[4], bRB[2], bXR[2];
    #pragma unroll
    for (int mf = 0; mf < 4; mf++) {
        uint32_t rb = (uint32_t)((wm * 64 + mf * 16 + a_row) * 64);
        aRB[mf] = rb; aXR[mf] = (rb >> 3) & 0x30u;
    }
    #pragma unroll
    for (int pf = 0; pf < 2; pf++) {
        uint32_t rb = (uint32_t)((wn * 32 + pf * 16 + b_row) * 64);
        bRB[pf] = rb; bXR[pf] = (rb >> 3) & 0x30u;
    }

    float d[4][4][4] = {};
    issue(0);

    #pragma unroll 1
    for (int c = 0; c < NB1; c++) {
        CP_WAIT(0);
        __syncthreads();
        issue(c + 1);
        const uint32_t st = sbase + (uint32_t)(c & 1) * (uint32_t)STG1;
        #pragma unroll
        for (int kk = 0; kk < 2; kk++) {
            const uint32_t ck = (uint32_t)(kk << 5);
            // cache W0,W1 fragments (16 regs)
            uint32_t b[2][4][2];
            #pragma unroll
            for (int j = 0; j < 2; j++) {
                #pragma unroll
                for (int pf = 0; pf < 2; pf++) {
                    uint32_t r0, r1, r2, r3;
                    LDSM_X4(r0, r1, r2, r3,
                            st + (2 + j) * TILE_N + bRB[pf] + ((ck + b_kb) ^ bXR[pf]));
                    b[j][2 * pf][0] = r0; b[j][2 * pf][1] = r1;
                    b[j][2 * pf + 1][0] = r2; b[j][2 * pf + 1][1] = r3;
                }
            }
            #pragma unroll
            for (int mf = 0; mf < 4; mf++) {
                uint32_t a0[4], a1[4];
                LDSM_X4(a0[0], a0[1], a0[2], a0[3],
                        st + aRB[mf] + ((ck + a_kb) ^ aXR[mf]));
                LDSM_X4(a1[0], a1[1], a1[2], a1[3],
                        st + TILE_N + aRB[mf] + ((ck + a_kb) ^ aXR[mf]));
                // order per d element: A0*W0, A1*W0, A2*W1s (bit-identical to prior rounds)
                #pragma unroll
                for (int nf = 0; nf < 4; nf++) MMA16816(d[mf][nf], a0, b[0][nf][0], b[0][nf][1]);
                #pragma unroll
                for (int nf = 0; nf < 4; nf++) MMA16816(d[mf][nf], a1, b[0][nf][0], b[0][nf][1]);
                #pragma unroll
                for (int r = 0; r < 4; r++) HMUL2(a0[r], a0[r], 0x14001400u);
                #pragma unroll
                for (int nf = 0; nf < 4; nf++) MMA16816(d[mf][nf], a0, b[1][nf][0], b[1][nf][1]);
            }
        }
        __syncthreads();
    }

    float* P = g_p1 + (size_t)(t & 1) * P1SZ + (size_t)z * Bn * Hn + n0;
    const int r0 = lane >> 2, c0 = (lane & 3) * 2;
    #pragma unroll
    for (int mf = 0; mf < 4; mf++) {
        #pragma unroll
        for (int nf = 0; nf < 4; nf++) {
            int m = wm * 64 + mf * 16 + r0;
            int n = wn * 32 + nf * 8 + c0;
            *reinterpret_cast<float2*>(&P[(size_t)m * Hn + n]) =
                make_float2(d[mf][nf][0], d[mf][nf][1]);
            *reinterpret_cast<float2*>(&P[(size_t)(m + 8) * Hn + n]) =
                make_float2(d[mf][nf][2], d[mf][nf][3]);
        }
    }
}

// ================= GEMM2 + fuse1(t) pre-sync; fuse2(t-1) post-epilogue =================
// bid in [0,128): nt = bid>>5, z = bid&31. smem tiles (16KB each):
// 0..3 = W0c0,W1c0,W0c1,W1c1 ; 4 = S ; 5 = Ss
__device__ __forceinline__ void gemm2_fused(float* __restrict__ out, int t, int bid, uint32_t sbase) {
    const int tid  = threadIdx.x;
    const int wid  = tid >> 5, lane = tid & 31;
    const int wm   = wid & 1, wn = wid >> 1;      // 2m x 4n, warp tile 64x32
    const int nt   = bid >> 5, z = bid & 31;
    const int n0   = nt * 128;
    const int kbase = z * 128;

    // W loads first (overlap with fuse phase)
    #pragma unroll
    for (int c = 0; c < NB2; c++)
        #pragma unroll
        for (int seg = 0; seg < 2; seg++)
            cp_tile128(sbase + (c * 2 + seg) * TILE_W,
                       g_w2 + (size_t)n0 * K2W + seg * Hn + kbase + c * 64, K2W);
    CP_COMMIT();

    // ---- fuse1(t): this CTA updates hv row `bid` (1024 float4) ----
    {
        const bool  hp   = (t > 0);
        const float thrp = hp ? VTH * tanhf(GW * dec_f(g_maxh[t - 1])) : 0.f;
        constexpr int NF4 = Bn * Hn / 4;
        const float4* p14 = reinterpret_cast<const float4*>(g_p1 + (size_t)(t & 1) * P1SZ);
        float4* hv4 = reinterpret_cast<float4*>(g_hv);
        float lmax = -3.4e38f;
        #pragma unroll
        for (int q = 0; q < 4; q++) {
            int fi = bid * 1024 + q * 256 + tid;
            float4 s = p14[fi];
            #pragma unroll
            for (int zz = 1; zz < S1; zz++) {
                float4 p = p14[(size_t)zz * NF4 + fi];
                s.x += p.x; s.y += p.y; s.z += p.z; s.w += p.w;
            }
            float4 ho = hp ? hv4[fi] : make_float4(0.f, 0.f, 0.f, 0.f);
            float4 hn;
            hn.x = ho.x * ((hp && ho.x > thrp) ? 0.f : VDEC) + s.x;
            hn.y = ho.y * ((hp && ho.y > thrp) ? 0.f : VDEC) + s.y;
            hn.z = ho.z * ((hp && ho.z > thrp) ? 0.f : VDEC) + s.z;
            hn.w = ho.w * ((hp && ho.w > thrp) ? 0.f : VDEC) + s.w;
            hv4[fi] = hn;
            lmax = fmaxf(lmax, fmaxf(fmaxf(hn.x, hn.y), fmaxf(hn.z, hn.w)));
        }
        float bm = block_max256(lmax);
        if (tid == 0) atomicMax(&g_maxh[t], enc_f(bm));
    }

    // ---- device-wide sync across the 128 gemm2 CTAs (all wave-1 resident) ----
    __threadfence();
    __syncthreads();
    if (tid == 0) {
        atomicAdd(&g_cc[t], 1);
        while (((volatile int*)g_cc)[t] < 128) __nanosleep(64);
    }
    __syncthreads();

    const float thr = VTH * tanhf(GW * dec_f(*((volatile unsigned*)&g_maxh[t])));
    CP_WAIT(0);
    __syncthreads();

    const int grp = lane >> 3, lrow = lane & 7;
    const int a_row = lrow + ((grp & 1) << 3);
    const uint32_t a_kb = (uint32_t)((grp >> 1) << 4);
    const int b_row = lrow + ((grp >> 1) << 3);
    const uint32_t b_kb = (uint32_t)((grp & 1) << 4);
    uint32_t aRB[4], aXR[4], bRB[2], bXR[2];
    #pragma unroll
    for (int mf = 0; mf < 4; mf++) {
        uint32_t rb = (uint32_t)((wm * 64 + mf * 16 + a_row) * 128);
        aRB[mf] = rb; aXR[mf] = (rb >> 3) & 0x70u;
    }
    #pragma unroll
    for (int pf = 0; pf < 2; pf++) {
        uint32_t rb = (uint32_t)((wn * 32 + pf * 16 + b_row) * 128);
        bRB[pf] = rb; bXR[pf] = (rb >> 3) & 0x70u;
    }

    float d[4][4][4] = {};
    #pragma unroll 1
    for (int c = 0; c < NB2; c++) {
        // convert spikes S (1.0) and Ss (2^-10) into tiles 4,5 (L1-bypassed hv reads)
        const uint32_t ta  = sbase + 4 * TILE_W;
        const uint32_t tas = sbase + 5 * TILE_W;
        #pragma unroll
        for (int p = 0; p < 4; p++) {
            int id = p * 256 + tid;
            int row = id >> 3, g = id & 7;
            const float4* sp = reinterpret_cast<const float4*>(
                g_hv + (size_t)row * Hn + kbase + c * 64 + g * 8);
            float4 va = __ldcg(sp), vb = __ldcg(sp + 1);
            uint32_t m0 = (va.x > thr ? 0x0001u : 0u) | (va.y > thr ? 0x00010000u : 0u);
            uint32_t m1 = (va.z > thr ? 0x0001u : 0u) | (va.w > thr ? 0x00010000u : 0u);
            uint32_t m2 = (vb.x > thr ? 0x0001u : 0u) | (vb.y > thr ? 0x00010000u : 0u);
            uint32_t m3 = (vb.z > thr ? 0x0001u : 0u) | (vb.w > thr ? 0x00010000u : 0u);
            uint32_t off = (uint32_t)(row * 128 + g * 16);
            off ^= (off >> 3) & 0x70u;
            asm volatile("st.shared.v4.b32 [%0], {%1,%2,%3,%4};"
                :: "r"(ta + off), "r"(m0 * 0x3C00u), "r"(m1 * 0x3C00u),
                   "r"(m2 * 0x3C00u), "r"(m3 * 0x3C00u) : "memory");
            asm volatile("st.shared.v4.b32 [%0], {%1,%2,%3,%4};"
                :: "r"(tas + off), "r"(m0 * 0x1400u), "r"(m1 * 0x1400u),
                   "r"(m2 * 0x1400u), "r"(m3 * 0x1400u) : "memory");
        }
        __syncthreads();
        #pragma unroll
        for (int kk = 0; kk < 4; kk++) {
            const uint32_t ck = (uint32_t)(kk << 5);
            #pragma unroll
            for (int p = 0; p < 2; p++) {  // (S,W0c), (Ss,W1c)
                uint32_t a[4][4];
                #pragma unroll
                for (int mf = 0; mf < 4; mf++)
                    LDSM_X4(a[mf][0], a[mf][1], a[mf][2], a[mf][3],
                            sbase + (4 + p) * TILE_W + aRB[mf] + ((ck + a_kb) ^ aXR[mf]));
                uint32_t b[4][2];
                #pragma unroll
                for (int pf = 0; pf < 2; pf++) {
                    uint32_t r0, r1, r2, r3;
                    LDSM_X4(r0, r1, r2, r3,
                            sbase + (c * 2 + p) * TILE_W + bRB[pf] + ((ck + b_kb) ^ bXR[pf]));
                    b[2 * pf][0] = r0; b[2 * pf][1] = r1;
                    b[2 * pf + 1][0] = r2; b[2 * pf + 1][1] = r3;
                }
                #pragma unroll
                for (int mf = 0; mf < 4; mf++)
                    #pragma unroll
                    for (int nf = 0; nf < 4; nf++)
                        MMA16816(d[mf][nf], a[mf], b[nf][0], b[nf][1]);
            }
        }
        __syncthreads();
    }

    float* P = g_p2 + (size_t)(t & 1) * P2SZ + (size_t)z * Bn * On + n0;
    const int r0 = lane >> 2, c0 = (lane & 3) * 2;
    #pragma unroll
    for (int mf = 0; mf < 4; mf++) {
        #pragma unroll
        for (int nf = 0; nf < 4; nf++) {
            int m = wm * 64 + mf * 16 + r0;
            int n = wn * 32 + nf * 8 + c0;
            *reinterpret_cast<float2*>(&P[(size_t)m * On + n]) =
                make_float2(d[mf][nf][0], d[mf][nf][1]);
            *reinterpret_cast<float2*>(&P[(size_t)(m + 8) * On + n]) =
                make_float2(d[mf][nf][2], d[mf][nf][3]);
        }
    }

    // ---- fuse2(t-1) AFTER the epilogue (off the pre-sync critical path) ----
    if (t > 0 && bid < 64) {
        __syncthreads();
        const int pt = t - 1;
        const bool  hp   = (pt > 0);
        const float thrp = hp ? VTH * tanhf(GW * dec_f(g_maxo[pt - 1])) : 0.f;
        constexpr int NF4 = Bn * On / 4;
        const int fi = bid * 256 + tid;
        const float4* p24 = reinterpret_cast<const float4*>(g_p2 + (size_t)(pt & 1) * P2SZ);
        float4* ov4 = reinterpret_cast<float4*>(g_ov);
        float4* o4  = reinterpret_cast<float4*>(out);
        float4 s = p24[fi];
        #pragma unroll
        for (int zz = 1; zz < S2; zz++) {
            float4 p = p24[(size_t)zz * NF4 + fi];
            s.x += p.x; s.y += p.y; s.z += p.z; s.w += p.w;
        }
        float4 oo = hp ? ov4[fi] : make_float4(0.f, 0.f, 0.f, 0.f);
        float4 os;
        os.x = (hp && oo.x > thrp) ? 1.f : 0.f;
        os.y = (hp && oo.y > thrp) ? 1.f : 0.f;
        os.z = (hp && oo.z > thrp) ? 1.f : 0.f;
        os.w = (hp && oo.w > thrp) ? 1.f : 0.f;
        float4 acc = hp ? o4[fi] : make_float4(0.f, 0.f, 0.f, 0.f);
        acc.x += os.x; acc.y += os.y; acc.z += os.z; acc.w += os.w;
        o4[fi] = acc;
        float4 nv;
        nv.x = oo.x * ((os.x > 0.f) ? 0.f : VDEC) + s.x;
        nv.y = oo.y * ((os.y > 0.f) ? 0.f : VDEC) + s.y;
        nv.z = oo.z * ((os.z > 0.f) ? 0.f : VDEC) + s.z;
        nv.w = oo.w * ((os.w > 0.f) ? 0.f : VDEC) + s.w;
        ov4[fi] = nv;
        float lmax = fmaxf(fmaxf(nv.x, nv.y), fmaxf(nv.z, nv.w));
        float bm = block_max256(lmax);
        if (tid == 0) atomicMax(&g_maxo[pt], enc_f(bm));
    }
}

// ---------------- kernels ----------------
__global__ void __launch_bounds__(256, 2) gemm1_k(int t) {
    extern __shared__ char smem[];
    gemm1_body(t, blockIdx.x, smem_to_u32(smem));
}
__global__ void __launch_bounds__(256, 2) combo_k(float* __restrict__ out, int t) {
    extern __shared__ char smem[];
    const uint32_t sbase = smem_to_u32(smem);
    if (blockIdx.x < 128) {
        gemm2_fused(out, t, blockIdx.x, sbase);
    } else if (t + 1 < Tn) {
        gemm1_body(t + 1, blockIdx.x - 128, sbase);
    }
}

// ---------------- prep kernels ----------------
__global__ void reset_k() {
    int i = threadIdx.x;
    if (i < Tn) { g_maxh[i] = 0x007FFFFFu; g_maxo[i] = 0x007FFFFFu; g_cc[i] = 0; }
}

__device__ __forceinline__ void split2(float v, __half& s0, __half& s1) {
    s0 = __float2half_rn(v);
    s1 = __float2half_rn(v - __half2float(s0));
}
__device__ __forceinline__ void split_w(float v, __half& w0, __half& w1s) {
    w0 = __float2half_rn(v);
    w1s = __float2half_rn((v - __half2float(w0)) * 1024.0f);
}

// spike_data [B][I][T] fp32 -> g_a1 [T][B][ A0 | A1 ]
__global__ void prep_a1_k(const float* __restrict__ sd) {
    __shared__ float tile[32][33];
    int b = blockIdx.z, i0 = blockIdx.y * 32, t0 = blockIdx.x * 32;
    int tx = threadIdx.x, ty = threadIdx.y;
    #pragma unroll
    for (int j = 0; j < 32; j += 8) {
        int i = i0 + ty + j, tt = t0 + tx;
        tile[ty + j][tx] = (tt < Tn) ? sd[((size_t)b * In + i) * Tn + tt] : 0.f;
    }
    __syncthreads();
    #pragma unroll
    for (int j = 0; j < 32; j += 8) {
        int tt = t0 + ty + j, i = i0 + tx;
        if (tt < Tn) {
            __half a0, a1;
            split2(tile[tx][ty + j], a0, a1);
            size_t base = ((size_t)tt * Bn + b) * K1A;
            g_a1[base + 0 * In + i] = a0;
            g_a1[base + 1 * In + i] = a1;
        }
    }
}

__global__ void conv_w1_k(const float* __restrict__ w) {
    int idx = blockIdx.x * 256 + threadIdx.x;  // exact Hn*In
    __half w0, w1s;
    split_w(w[idx], w0, w1s);
    int h = idx >> 10, k = idx & 1023;
    size_t base = (size_t)h * K1W;
    g_w1[base + 0 * In + k] = w0;
    g_w1[base + 1 * In + k] = w1s;
}
__global__ void conv_w2_k(const float* __restrict__ w) {
    int idx = blockIdx.x * 256 + threadIdx.x;  // exact On*Hn
    __half w0, w1s;
    split_w(w[idx], w0, w1s);
    int o = idx >> 12, k = idx & 4095;
    size_t base = (size_t)o * K2W;
    g_w2[base + 0 * Hn + k] = w0;
    g_w2[base + 1 * Hn + k] = w1s;
}

// ---------------- standalone fuse2 (t=99) + final ----------------
__global__ __launch_bounds__(256) void fuse2_k(float* __restrict__ out, int t) {
    const bool  hp   = (t > 0);
    const float thrp = hp ? VTH * tanhf(GW * dec_f(g_maxo[t - 1])) : 0.f;
    constexpr int NF4 = Bn * On / 4;
    int fi = blockIdx.x * 256 + threadIdx.x;
    const float4* p24 = reinterpret_cast<const float4*>(g_p2 + (size_t)(t & 1) * P2SZ);
    float4* ov4 = reinterpret_cast<float4*>(g_ov);
    float4* o4  = reinterpret_cast<float4*>(out);
    float4 s = p24[fi];
    #pragma unroll
    for (int zz = 1; zz < S2; zz++) {
        float4 p = p24[(size_t)zz * NF4 + fi];
        s.x += p.x; s.y += p.y; s.z += p.z; s.w += p.w;
    }
    float4 oo = hp ? ov4[fi] : make_float4(0.f, 0.f, 0.f, 0.f);
    float4 os;
    os.x = (hp && oo.x > thrp) ? 1.f : 0.f;
    os.y = (hp && oo.y > thrp) ? 1.f : 0.f;
    os.z = (hp && oo.z > thrp) ? 1.f : 0.f;
    os.w = (hp && oo.w > thrp) ? 1.f : 0.f;
    float4 acc = hp ? o4[fi] : make_float4(0.f, 0.f, 0.f, 0.f);
    acc.x += os.x; acc.y += os.y; acc.z += os.z; acc.w += os.w;
    o4[fi] = acc;
    float4 nv;
    nv.x = oo.x * ((os.x > 0.f) ? 0.f : VDEC) + s.x;
    nv.y = oo.y * ((os.y > 0.f) ? 0.f : VDEC) + s.y;
    nv.z = oo.z * ((os.z > 0.f) ? 0.f : VDEC) + s.z;
    nv.w = oo.w * ((os.w > 0.f) ? 0.f : VDEC) + s.w;
    ov4[fi] = nv;
    float lmax = fmaxf(fmaxf(nv.x, nv.y), fmaxf(nv.z, nv.w));
    float bm = block_max256(lmax);
    if (threadIdx.x == 0) atomicMax(&g_maxo[t], enc_f(bm));
}

__global__ __launch_bounds__(256) void final_k(float* __restrict__ out) {
    const float thr = VTH * tanhf(GW * dec_f(g_maxo[Tn - 1]));
    int fi = blockIdx.x * 256 + threadIdx.x;
    float4 ov = reinterpret_cast<const float4*>(g_ov)[fi];
    float4 o  = reinterpret_cast<float4*>(out)[fi];
    o.x += (ov.x > thr) ? 1.f : 0.f;
    o.y += (ov.y > thr) ? 1.f : 0.f;
    o.z += (ov.z > thr) ? 1.f : 0.f;
    o.w += (ov.w > thr) ? 1.f : 0.f;
    reinterpret_cast<float4*>(out)[fi] = o;
}

// ---------------- launch ----------------
extern "C" void kernel_launch(void* const* d_in, const int* in_sizes, int n_in,
                              void* d_out, int out_size) {
    const float* sd    = (const float*)d_in[0];  // spike_data [B][I][T]
    const float* w_hid = (const float*)d_in[5];  // [H][I]
    const float* w_out = (const float*)d_in[6];  // [O][H]
    float* out = (float*)d_out;                  // [B][O]

    cudaFuncSetAttribute((const void*)gemm1_k, cudaFuncAttributeMaxDynamicSharedMemorySize, SMEM_C);
    cudaFuncSetAttribute((const void*)combo_k, cudaFuncAttributeMaxDynamicSharedMemorySize, SMEM_C);

    reset_k<<<1, 128>>>();
    prep_a1_k<<<dim3((Tn + 31) / 32, In / 32, Bn), dim3(32, 8)>>>(sd);
    conv_w1_k<<<Hn * In / 256, 256>>>(w_hid);
    conv_w2_k<<<On * Hn / 256, 256>>>(w_out);

    gemm1_k<<<NT1, 256, SMEM_C>>>(0);
    for (int t = 0; t < Tn; t++)
        combo_k<<<256, 256, SMEM_C>>>(out, t);
    fuse2_k<<<64, 256>>>(out, Tn - 1);
    final_k<<<64, 256>>>(out);
}

// round 14
// speedup vs baseline: 1.1617x; 1.1617x over previous
#include <cuda_runtime.h>
#include <cuda_fp16.h>
#include <cstdint>

// ---------------- problem constants ----------------
constexpr int Bn = 128;   // batch (GEMM M)
constexpr int In = 1024;  // input features
constexpr int Hn = 4096;  // hidden
constexpr int On = 512;   // output
constexpr int Tn = 100;   // timesteps
constexpr int S1 = 8;     // k-splits GEMM1 (base K 1024 -> 128/CTA)
constexpr int S2 = 32;    // k-splits GEMM2 (base K 4096 -> 128/CTA)
constexpr int NB1 = 2;    // 64-col chunks per CTA, GEMM1
constexpr int NB2 = 2;    // 64-col chunks per CTA, GEMM2
constexpr int NT1 = 512;  // gemm1 tiles per step (2m x 32n x 8z)
constexpr int K1A = 2 * In;   // g_a1 row: [A0 | A1]
constexpr int K1W = 2 * In;   // g_w1 row: [W0 | W1s]
constexpr int K2W = 2 * Hn;   // g_w2 row: [W0 | W1s]

constexpr int TILE_W = 16384;  // 128x64 fp16 tile
constexpr int TILE_A = 8192;   // 64x64 fp16 tile
constexpr int STG1   = 2 * TILE_A + 2 * TILE_W;  // 48KB: A0,A1,W0,W1s
constexpr int SMEM_C = 2 * STG1;                 // 96KB (gemm2 path: 6x16KB = 96KB)

constexpr size_t P1SZ = (size_t)S1 * Bn * Hn;
constexpr size_t P2SZ = (size_t)S2 * Bn * On;

constexpr float VDEC = 0.5f;
constexpr float VTH  = 0.3f;
constexpr float GW   = 0.3f;

// ---------------- device scratch ----------------
__device__ __half g_a1[(size_t)Tn * Bn * K1A];  // [T][B][2048] 52.4MB
__device__ __half g_w1[(size_t)Hn * K1W];       // [H][2048] 16.8MB
__device__ __half g_w2[(size_t)On * K2W];       // [O][8192] 8.4MB
__device__ float    g_hv[Bn * Hn];
__device__ float    g_ov[Bn * On];
__device__ float    g_p1[2 * P1SZ];             // double-buffered by t&1 (32MB)
__device__ float    g_p2[2 * P2SZ];             // double-buffered by t&1
__device__ unsigned g_maxh[Tn];
__device__ unsigned g_maxo[Tn];
__device__ int      g_cc[Tn];                   // per-step gemm2 arrival counters

// ---------------- helpers ----------------
__device__ __forceinline__ unsigned enc_f(float x) {
    unsigned u = __float_as_uint(x);
    return (u & 0x80000000u) ? ~u : (u | 0x80000000u);
}
__device__ __forceinline__ float dec_f(unsigned k) {
    unsigned u = (k & 0x80000000u) ? (k & 0x7FFFFFFFu) : ~k;
    return __uint_as_float(u);
}
__device__ __forceinline__ float block_max256(float v) {
    #pragma unroll
    for (int o = 16; o > 0; o >>= 1)
        v = fmaxf(v, __shfl_xor_sync(0xffffffffu, v, o));
    __shared__ float red[8];
    int w = threadIdx.x >> 5;
    if ((threadIdx.x & 31) == 0) red[w] = v;
    __syncthreads();
    if (threadIdx.x == 0) {
        #pragma unroll
        for (int i = 1; i < 8; i++) v = fmaxf(v, red[i]);
    }
    return v;
}
__device__ __forceinline__ uint32_t smem_to_u32(const void* p) {
    uint32_t a;
    asm("{ .reg .u64 t; cvta.to.shared.u64 t, %1; cvt.u32.u64 %0, t; }" : "=r"(a) : "l"(p));
    return a;
}

#define LDSM_X4(r0, r1, r2, r3, addr) \
    asm volatile("ldmatrix.sync.aligned.m8n8.x4.shared.b16 {%0,%1,%2,%3}, [%4];" \
        : "=r"(r0), "=r"(r1), "=r"(r2), "=r"(r3) : "r"(addr))

#define MMA16816(d, a, b0, b1) \
    asm volatile("mma.sync.aligned.m16n8k16.row.col.f32.f16.f16.f32 " \
        "{%0,%1,%2,%3}, {%4,%5,%6,%7}, {%8,%9}, {%0,%1,%2,%3};" \
        : "+f"((d)[0]), "+f"((d)[1]), "+f"((d)[2]), "+f"((d)[3]) \
        : "r"((a)[0]), "r"((a)[1]), "r"((a)[2]), "r"((a)[3]), "r"(b0), "r"(b1))

#define HMUL2(o, x, y) asm("mul.f16x2 %0, %1, %2;" : "=r"(o) : "r"(x), "r"(y))

#define CP_ASYNC16(sdst, gsrc) \
    asm volatile("cp.async.cg.shared.global [%0], [%1], 16;" :: "r"(sdst), "l"(gsrc) : "memory")
#define CP_COMMIT() asm volatile("cp.async.commit_group;" ::: "memory")
#define CP_WAIT(n)  asm volatile("cp.async.wait_group %0;" :: "n"(n) : "memory")

// 128 rows x 64 fp16 tile (128B rows, SW128 swizzle)
__device__ __forceinline__ void cp_tile128(uint32_t sdst, const __half* __restrict__ src, int ld) {
    int tid = threadIdx.x;
    #pragma unroll
    for (int p = 0; p < 4; p++) {
        int id  = p * 256 + tid;
        int row = id >> 3, g = id & 7;
        uint32_t off = (uint32_t)(row * 128 + g * 16);
        off ^= (off >> 3) & 0x70u;
        CP_ASYNC16(sdst + off, src + (size_t)row * ld + g * 8);
    }
}
// 64 rows x 64 fp16 tile
__device__ __forceinline__ void cp_tile64(uint32_t sdst, const __half* __restrict__ src, int ld) {
    int tid = threadIdx.x;
    #pragma unroll
    for (int p = 0; p < 2; p++) {
        int id  = p * 256 + tid;
        int row = id >> 3, g = id & 7;
        uint32_t off = (uint32_t)(row * 128 + g * 16);
        off ^= (off >> 3) & 0x70u;
        CP_ASYNC16(sdst + off, src + (size_t)row * ld + g * 8);
    }
}

// ================= GEMM1 body: 64x128 output tile, 3-product fp16 split =================
// tile id in [0,512): mt = id&1 (M half), nt = (id>>1)&31, z = id>>6 (0..7)
__device__ __forceinline__ void gemm1_body(int t, int bid_g, uint32_t sbase) {
    const int tid  = threadIdx.x;
    const int wid  = tid >> 5, lane = tid & 31;
    const int wm   = wid & 1, wn = wid >> 1;      // 2m x 4n, warp tile 32x32
    const int mt   = bid_g & 1;
    const int nt   = (bid_g >> 1) & 31;
    const int z    = bid_g >> 6;                  // 0..7
    const int m0   = mt * 64;
    const int n0   = nt * 128;
    const int kbase = z * 128;

    const __half* Abase = g_a1 + (size_t)t * Bn * K1A + (size_t)m0 * K1A;

    auto issue = [&](int c) {
        if (c < NB1) {
            uint32_t st = sbase + (uint32_t)(c & 1) * (uint32_t)STG1;
            int kk = kbase + c * 64;
            cp_tile64(st,              Abase + 0 * In + kk, K1A);
            cp_tile64(st + TILE_A,     Abase + 1 * In + kk, K1A);
            cp_tile128(st + 2 * TILE_A,          g_w1 + (size_t)n0 * K1W + 0 * In + kk, K1W);
            cp_tile128(st + 2 * TILE_A + TILE_W, g_w1 + (size_t)n0 * K1W + 1 * In + kk, K1W);
        }
        CP_COMMIT();
    };

    const int grp = lane >> 3, lrow = lane & 7;
    const int a_row = lrow + ((grp & 1) << 3);
    const uint32_t a_kb = (uint32_t)((grp >> 1) << 4);
    const int b_row = lrow + ((grp >> 1) << 3);
    const uint32_t b_kb = (uint32_t)((grp & 1) << 4);
    uint32_t aRB[2], aXR[2], bRB[2], bXR[2];
    #pragma unroll
    for (int mf = 0; mf < 2; mf++) {
        uint32_t rb = (uint32_t)((wm * 32 + mf * 16 + a_row) * 128);
        aRB[mf] = rb; aXR[mf] = (rb >> 3) & 0x70u;
    }
    #pragma unroll
    for (int pf = 0; pf < 2; pf++) {
        uint32_t rb = (uint32_t)((wn * 32 + pf * 16 + b_row) * 128);
        bRB[pf] = rb; bXR[pf] = (rb >> 3) & 0x70u;
    }

    float d[2][4][4] = {};
    issue(0);

    #pragma unroll 1
    for (int c = 0; c < NB1; c++) {
        CP_WAIT(0);
        __syncthreads();
        issue(c + 1);
        const uint32_t st = sbase + (uint32_t)(c & 1) * (uint32_t)STG1;
        #pragma unroll
        for (int kk = 0; kk < 4; kk++) {
            const uint32_t ck = (uint32_t)(kk << 5);
            uint32_t b[2][4][2];
            #pragma unroll
            for (int j = 0; j < 2; j++) {
                #pragma unroll
                for (int pf = 0; pf < 2; pf++) {
                    uint32_t r0, r1, r2, r3;
                    LDSM_X4(r0, r1, r2, r3,
                            st + 2 * TILE_A + j * TILE_W + bRB[pf] + ((ck + b_kb) ^ bXR[pf]));
                    b[j][2 * pf][0] = r0; b[j][2 * pf][1] = r1;
                    b[j][2 * pf + 1][0] = r2; b[j][2 * pf + 1][1] = r3;
                }
            }
            uint32_t a0[2][4], a1[2][4], a2[2][4];
            #pragma unroll
            for (int mf = 0; mf < 2; mf++) {
                LDSM_X4(a0[mf][0], a0[mf][1], a0[mf][2], a0[mf][3],
                        st + aRB[mf] + ((ck + a_kb) ^ aXR[mf]));
                LDSM_X4(a1[mf][0], a1[mf][1], a1[mf][2], a1[mf][3],
                        st + TILE_A + aRB[mf] + ((ck + a_kb) ^ aXR[mf]));
                #pragma unroll
                for (int r = 0; r < 4; r++) HMUL2(a2[mf][r], a0[mf][r], 0x14001400u);
            }
            #pragma unroll
            for (int mf = 0; mf < 2; mf++)
                #pragma unroll
                for (int nf = 0; nf < 4; nf++) {
                    MMA16816(d[mf][nf], a0[mf], b[0][nf][0], b[0][nf][1]);
                    MMA16816(d[mf][nf], a1[mf], b[0][nf][0], b[0][nf][1]);
                    MMA16816(d[mf][nf], a2[mf], b[1][nf][0], b[1][nf][1]);
                }
        }
        __syncthreads();
    }

    float* P = g_p1 + (size_t)(t & 1) * P1SZ + (size_t)z * Bn * Hn + n0;
    const int r0 = lane >> 2, c0 = (lane & 3) * 2;
    #pragma unroll
    for (int mf = 0; mf < 2; mf++) {
        #pragma unroll
        for (int nf = 0; nf < 4; nf++) {
            int m = m0 + wm * 32 + mf * 16 + r0;
            int n = wn * 32 + nf * 8 + c0;
            *reinterpret_cast<float2*>(&P[(size_t)m * Hn + n]) =
                make_float2(d[mf][nf][0], d[mf][nf][1]);
            *reinterpret_cast<float2*>(&P[(size_t)(m + 8) * Hn + n]) =
                make_float2(d[mf][nf][2], d[mf][nf][3]);
        }
    }
}

// ================= GEMM2 + fuse1(t) pre-sync; fuse2(t-1) post-epilogue =================
// bid in [0,128): nt = bid>>5, z = bid&31. smem tiles (16KB each):
// 0..3 = W0c0,W1c0,W0c1,W1c1 ; 4 = S ; 5 = Ss
__device__ __forceinline__ void gemm2_fused(float* __restrict__ out, int t, int bid, uint32_t sbase) {
    const int tid  = threadIdx.x;
    const int wid  = tid >> 5, lane = tid & 31;
    const int wm   = wid & 1, wn = wid >> 1;      // 2m x 4n, warp tile 64x32
    const int nt   = bid >> 5, z = bid & 31;
    const int n0   = nt * 128;
    const int kbase = z * 128;

    // W loads first (overlap with fuse phase)
    #pragma unroll
    for (int c = 0; c < NB2; c++)
        #pragma unroll
        for (int seg = 0; seg < 2; seg++)
            cp_tile128(sbase + (c * 2 + seg) * TILE_W,
                       g_w2 + (size_t)n0 * K2W + seg * Hn + kbase + c * 64, K2W);
    CP_COMMIT();

    // ---- fuse1(t): this CTA updates hv row `bid` (1024 float4) ----
    {
        const bool  hp   = (t > 0);
        const float thrp = hp ? VTH * tanhf(GW * dec_f(g_maxh[t - 1])) : 0.f;
        constexpr int NF4 = Bn * Hn / 4;
        const float4* p14 = reinterpret_cast<const float4*>(g_p1 + (size_t)(t & 1) * P1SZ);
        float4* hv4 = reinterpret_cast<float4*>(g_hv);
        float lmax = -3.4e38f;
        #pragma unroll
        for (int q = 0; q < 4; q++) {
            int fi = bid * 1024 + q * 256 + tid;
            float4 s = p14[fi];
            #pragma unroll
            for (int zz = 1; zz < S1; zz++) {
                float4 p = p14[(size_t)zz * NF4 + fi];
                s.x += p.x; s.y += p.y; s.z += p.z; s.w += p.w;
            }
            float4 ho = hp ? hv4[fi] : make_float4(0.f, 0.f, 0.f, 0.f);
            float4 hn;
            hn.x = ho.x * ((hp && ho.x > thrp) ? 0.f : VDEC) + s.x;
            hn.y = ho.y * ((hp && ho.y > thrp) ? 0.f : VDEC) + s.y;
            hn.z = ho.z * ((hp && ho.z > thrp) ? 0.f : VDEC) + s.z;
            hn.w = ho.w * ((hp && ho.w > thrp) ? 0.f : VDEC) + s.w;
            hv4[fi] = hn;
            lmax = fmaxf(lmax, fmaxf(fmaxf(hn.x, hn.y), fmaxf(hn.z, hn.w)));
        }
        float bm = block_max256(lmax);
        if (tid == 0) atomicMax(&g_maxh[t], enc_f(bm));
    }

    // ---- device-wide sync across the 128 gemm2 CTAs (all wave-1 resident) ----
    __threadfence();
    __syncthreads();
    if (tid == 0) {
        atomicAdd(&g_cc[t], 1);
        while (((volatile int*)g_cc)[t] < 128) __nanosleep(64);
    }
    __syncthreads();

    const float thr = VTH * tanhf(GW * dec_f(*((volatile unsigned*)&g_maxh[t])));
    CP_WAIT(0);
    __syncthreads();

    const int grp = lane >> 3, lrow = lane & 7;
    const int a_row = lrow + ((grp & 1) << 3);
    const uint32_t a_kb = (uint32_t)((grp >> 1) << 4);
    const int b_row = lrow + ((grp >> 1) << 3);
    const uint32_t b_kb = (uint32_t)((grp & 1) << 4);
    uint32_t aRB[4], aXR[4], bRB[2], bXR[2];
    #pragma unroll
    for (int mf = 0; mf < 4; mf++) {
        uint32_t rb = (uint32_t)((wm * 64 + mf * 16 + a_row) * 128);
        aRB[mf] = rb; aXR[mf] = (rb >> 3) & 0x70u;
    }
    #pragma unroll
    for (int pf = 0; pf < 2; pf++) {
        uint32_t rb = (uint32_t)((wn * 32 + pf * 16 + b_row) * 128);
        bRB[pf] = rb; bXR[pf] = (rb >> 3) & 0x70u;
    }

    float d[4][4][4] = {};
    #pragma unroll 1
    for (int c = 0; c < NB2; c++) {
        // convert spikes S (1.0) and Ss (2^-10) into tiles 4,5 (L1-bypassed hv reads)
        const uint32_t ta  = sbase + 4 * TILE_W;
        const uint32_t tas = sbase + 5 * TILE_W;
        #pragma unroll
        for (int p = 0; p < 4; p++) {
            int id = p * 256 + tid;
            int row = id >> 3, g = id & 7;
            const float4* sp = reinterpret_cast<const float4*>(
                g_hv + (size_t)row * Hn + kbase + c * 64 + g * 8);
            float4 va = __ldcg(sp), vb = __ldcg(sp + 1);
            uint32_t m0 = (va.x > thr ? 0x0001u : 0u) | (va.y > thr ? 0x00010000u : 0u);
            uint32_t m1 = (va.z > thr ? 0x0001u : 0u) | (va.w > thr ? 0x00010000u : 0u);
            uint32_t m2 = (vb.x > thr ? 0x0001u : 0u) | (vb.y > thr ? 0x00010000u : 0u);
            uint32_t m3 = (vb.z > thr ? 0x0001u : 0u) | (vb.w > thr ? 0x00010000u : 0u);
            uint32_t off = (uint32_t)(row * 128 + g * 16);
            off ^= (off >> 3) & 0x70u;
            asm volatile("st.shared.v4.b32 [%0], {%1,%2,%3,%4};"
                :: "r"(ta + off), "r"(m0 * 0x3C00u), "r"(m1 * 0x3C00u),
                   "r"(m2 * 0x3C00u), "r"(m3 * 0x3C00u) : "memory");
            asm volatile("st.shared.v4.b32 [%0], {%1,%2,%3,%4};"
                :: "r"(tas + off), "r"(m0 * 0x1400u), "r"(m1 * 0x1400u),
                   "r"(m2 * 0x1400u), "r"(m3 * 0x1400u) : "memory");
        }
        __syncthreads();
        #pragma unroll
        for (int kk = 0; kk < 4; kk++) {
            const uint32_t ck = (uint32_t)(kk << 5);
            #pragma unroll
            for (int p = 0; p < 2; p++) {  // (S,W0c), (Ss,W1c)
                uint32_t a[4][4];
                #pragma unroll
                for (int mf = 0; mf < 4; mf++)
                    LDSM_X4(a[mf][0], a[mf][1], a[mf][2], a[mf][3],
                            sbase + (4 + p) * TILE_W + aRB[mf] + ((ck + a_kb) ^ aXR[mf]));
                uint32_t b[4][2];
                #pragma unroll
                for (int pf = 0; pf < 2; pf++) {
                    uint32_t r0, r1, r2, r3;
                    LDSM_X4(r0, r1, r2, r3,
                            sbase + (c * 2 + p) * TILE_W + bRB[pf] + ((ck + b_kb) ^ bXR[pf]));
                    b[2 * pf][0] = r0; b[2 * pf][1] = r1;
                    b[2 * pf + 1][0] = r2; b[2 * pf + 1][1] = r3;
                }
                #pragma unroll
                for (int mf = 0; mf < 4; mf++)
                    #pragma unroll
                    for (int nf = 0; nf < 4; nf++)
                        MMA16816(d[mf][nf], a[mf], b[nf][0], b[nf][1]);
            }
        }
        __syncthreads();
    }

    float* P = g_p2 + (size_t)(t & 1) * P2SZ + (size_t)z * Bn * On + n0;
    const int r0 = lane >> 2, c0 = (lane & 3) * 2;
    #pragma unroll
    for (int mf = 0; mf < 4; mf++) {
        #pragma unroll
        for (int nf = 0; nf < 4; nf++) {
            int m = wm * 64 + mf * 16 + r0;
            int n = wn * 32 + nf * 8 + c0;
            *reinterpret_cast<float2*>(&P[(size_t)m * On + n]) =
                make_float2(d[mf][nf][0], d[mf][nf][1]);
            *reinterpret_cast<float2*>(&P[(size_t)(m + 8) * On + n]) =
                make_float2(d[mf][nf][2], d[mf][nf][3]);
        }
    }

    // ---- fuse2(t-1) AFTER the epilogue (off the pre-sync critical path) ----
    if (t > 0 && bid < 64) {
        __syncthreads();
        const int pt = t - 1;
        const bool  hp   = (pt > 0);
        const float thrp = hp ? VTH * tanhf(GW * dec_f(g_maxo[pt - 1])) : 0.f;
        constexpr int NF4 = Bn * On / 4;
        const int fi = bid * 256 + tid;
        const float4* p24 = reinterpret_cast<const float4*>(g_p2 + (size_t)(pt & 1) * P2SZ);
        float4* ov4 = reinterpret_cast<float4*>(g_ov);
        float4* o4  = reinterpret_cast<float4*>(out);
        float4 s = p24[fi];
        #pragma unroll
        for (int zz = 1; zz < S2; zz++) {
            float4 p = p24[(size_t)zz * NF4 + fi];
            s.x += p.x; s.y += p.y; s.z += p.z; s.w += p.w;
        }
        float4 oo = hp ? ov4[fi] : make_float4(0.f, 0.f, 0.f, 0.f);
        float4 os;
        os.x = (hp && oo.x > thrp) ? 1.f : 0.f;
        os.y = (hp && oo.y > thrp) ? 1.f : 0.f;
        os.z = (hp && oo.z > thrp) ? 1.f : 0.f;
        os.w = (hp && oo.w > thrp) ? 1.f : 0.f;
        float4 acc = hp ? o4[fi] : make_float4(0.f, 0.f, 0.f, 0.f);
        acc.x += os.x; acc.y += os.y; acc.z += os.z; acc.w += os.w;
        o4[fi] = acc;
        float4 nv;
        nv.x = oo.x * ((os.x > 0.f) ? 0.f : VDEC) + s.x;
        nv.y = oo.y * ((os.y > 0.f) ? 0.f : VDEC) + s.y;
        nv.z = oo.z * ((os.z > 0.f) ? 0.f : VDEC) + s.z;
        nv.w = oo.w * ((os.w > 0.f) ? 0.f : VDEC) + s.w;
        ov4[fi] = nv;
        float lmax = fmaxf(fmaxf(nv.x, nv.y), fmaxf(nv.z, nv.w));
        float bm = block_max256(lmax);
        if (tid == 0) atomicMax(&g_maxo[pt], enc_f(bm));
    }
}

// ---------------- kernels ----------------
__global__ void __launch_bounds__(256, 2) gemm1_k(int t) {
    extern __shared__ char smem[];
    gemm1_body(t, blockIdx.x, smem_to_u32(smem));
}
__global__ void __launch_bounds__(256, 2) combo_k(float* __restrict__ out, int t) {
    extern __shared__ char smem[];
    const uint32_t sbase = smem_to_u32(smem);
    if (blockIdx.x < 128) {
        gemm2_fused(out, t, blockIdx.x, sbase);
    } else if (t + 1 < Tn) {
        gemm1_body(t + 1, blockIdx.x - 128, sbase);
    }
}

// ---------------- prep kernels ----------------
__global__ void reset_k() {
    int i = threadIdx.x;
    if (i < Tn) { g_maxh[i] = 0x007FFFFFu; g_maxo[i] = 0x007FFFFFu; g_cc[i] = 0; }
}

__device__ __forceinline__ void split2(float v, __half& s0, __half& s1) {
    s0 = __float2half_rn(v);
    s1 = __float2half_rn(v - __half2float(s0));
}
__device__ __forceinline__ void split_w(float v, __half& w0, __half& w1s) {
    w0 = __float2half_rn(v);
    w1s = __float2half_rn((v - __half2float(w0)) * 1024.0f);
}

// spike_data [B][I][T] fp32 -> g_a1 [T][B][ A0 | A1 ]
__global__ void prep_a1_k(const float* __restrict__ sd) {
    __shared__ float tile[32][33];
    int b = blockIdx.z, i0 = blockIdx.y * 32, t0 = blockIdx.x * 32;
    int tx = threadIdx.x, ty = threadIdx.y;
    #pragma unroll
    for (int j = 0; j < 32; j += 8) {
        int i = i0 + ty + j, tt = t0 + tx;
        tile[ty + j][tx] = (tt < Tn) ? sd[((size_t)b * In + i) * Tn + tt] : 0.f;
    }
    __syncthreads();
    #pragma unroll
    for (int j = 0; j < 32; j += 8) {
        int tt = t0 + ty + j, i = i0 + tx;
        if (tt < Tn) {
            __half a0, a1;
            split2(tile[tx][ty + j], a0, a1);
            size_t base = ((size_t)tt * Bn + b) * K1A;
            g_a1[base + 0 * In + i] = a0;
            g_a1[base + 1 * In + i] = a1;
        }
    }
}

__global__ void conv_w1_k(const float* __restrict__ w) {
    int idx = blockIdx.x * 256 + threadIdx.x;  // exact Hn*In
    __half w0, w1s;
    split_w(w[idx], w0, w1s);
    int h = idx >> 10, k = idx & 1023;
    size_t base = (size_t)h * K1W;
    g_w1[base + 0 * In + k] = w0;
    g_w1[base + 1 * In + k] = w1s;
}
__global__ void conv_w2_k(const float* __restrict__ w) {
    int idx = blockIdx.x * 256 + threadIdx.x;  // exact On*Hn
    __half w0, w1s;
    split_w(w[idx], w0, w1s);
    int o = idx >> 12, k = idx & 4095;
    size_t base = (size_t)o * K2W;
    g_w2[base + 0 * Hn + k] = w0;
    g_w2[base + 1 * Hn + k] = w1s;
}

// ---------------- standalone fuse2 (t=99) + final ----------------
__global__ __launch_bounds__(256) void fuse2_k(float* __restrict__ out, int t) {
    const bool  hp   = (t > 0);
    const float thrp = hp ? VTH * tanhf(GW * dec_f(g_maxo[t - 1])) : 0.f;
    constexpr int NF4 = Bn * On / 4;
    int fi = blockIdx.x * 256 + threadIdx.x;
    const float4* p24 = reinterpret_cast<const float4*>(g_p2 + (size_t)(t & 1) * P2SZ);
    float4* ov4 = reinterpret_cast<float4*>(g_ov);
    float4* o4  = reinterpret_cast<float4*>(out);
    float4 s = p24[fi];
    #pragma unroll
    for (int zz = 1; zz < S2; zz++) {
        float4 p = p24[(size_t)zz * NF4 + fi];
        s.x += p.x; s.y += p.y; s.z += p.z; s.w += p.w;
    }
    float4 oo = hp ? ov4[fi] : make_float4(0.f, 0.f, 0.f, 0.f);
    float4 os;
    os.x = (hp && oo.x > thrp) ? 1.f : 0.f;
    os.y = (hp && oo.y > thrp) ? 1.f : 0.f;
    os.z = (hp && oo.z > thrp) ? 1.f : 0.f;
    os.w = (hp && oo.w > thrp) ? 1.f : 0.f;
    float4 acc = hp ? o4[fi] : make_float4(0.f, 0.f, 0.f, 0.f);
    acc.x += os.x; acc.y += os.y; acc.z += os.z; acc.w += os.w;
    o4[fi] = acc;
    float4 nv;
    nv.x = oo.x * ((os.x > 0.f) ? 0.f : VDEC) + s.x;
    nv.y = oo.y * ((os.y > 0.f) ? 0.f : VDEC) + s.y;
    nv.z = oo.z * ((os.z > 0.f) ? 0.f : VDEC) + s.z;
    nv.w = oo.w * ((os.w > 0.f) ? 0.f : VDEC) + s.w;
    ov4[fi] = nv;
    float lmax = fmaxf(fmaxf(nv.x, nv.y), fmaxf(nv.z, nv.w));
    float bm = block_max256(lmax);
    if (threadIdx.x == 0) atomicMax(&g_maxo[t], enc_f(bm));
}

__global__ __launch_bounds__(256) void final_k(float* __restrict__ out) {
    const float thr = VTH * tanhf(GW * dec_f(g_maxo[Tn - 1]));
    int fi = blockIdx.x * 256 + threadIdx.x;
    float4 ov = reinterpret_cast<const float4*>(g_ov)[fi];
    float4 o  = reinterpret_cast<float4*>(out)[fi];
    o.x += (ov.x > thr) ? 1.f : 0.f;
    o.y += (ov.y > thr) ? 1.f : 0.f;
    o.z += (ov.z > thr) ? 1.f : 0.f;
    o.w += (ov.w > thr) ? 1.f : 0.f;
    reinterpret_cast<float4*>(out)[fi] = o;
}

// ---------------- launch ----------------
extern "C" void kernel_launch(void* const* d_in, const int* in_sizes, int n_in,
                              void* d_out, int out_size) {
    const float* sd    = (const float*)d_in[0];  // spike_data [B][I][T]
    const float* w_hid = (const float*)d_in[5];  // [H][I]
    const float* w_out = (const float*)d_in[6];  // [O][H]
    float* out = (float*)d_out;                  // [B][O]

    cudaFuncSetAttribute((const void*)gemm1_k, cudaFuncAttributeMaxDynamicSharedMemorySize, SMEM_C);
    cudaFuncSetAttribute((const void*)combo_k, cudaFuncAttributeMaxDynamicSharedMemorySize, SMEM_C);

    reset_k<<<1, 128>>>();
    prep_a1_k<<<dim3((Tn + 31) / 32, In / 32, Bn), dim3(32, 8)>>>(sd);
    conv_w1_k<<<Hn * In / 256, 256>>>(w_hid);
    conv_w2_k<<<On * Hn / 256, 256>>>(w_out);

    gemm1_k<<<NT1, 256, SMEM_C>>>(0);
    for (int t = 0; t < Tn; t++)
        combo_k<<<128 + NT1, 256, SMEM_C>>>(out, t);
    fuse2_k<<<64, 256>>>(out, Tn - 1);
    final_k<<<64, 256>>>(out);
}

// round 15
// speedup vs baseline: 1.2840x; 1.1053x over previous
#include <cuda_runtime.h>
#include <cuda_fp16.h>
#include <cstdint>

// ---------------- problem constants ----------------
constexpr int Bn = 128;   // batch (GEMM M)
constexpr int In = 1024;  // input features
constexpr int Hn = 4096;  // hidden
constexpr int On = 512;   // output
constexpr int Tn = 100;   // timesteps
constexpr int NS1 = 6;    // p1 partial slots (z0, z1, z2a, z2b|0, z3a, z3b)
constexpr int S2 = 32;    // k-splits GEMM2 (base K 4096 -> 128/CTA)
constexpr int NB2 = 2;    // 64-col chunks per CTA, GEMM2
constexpr int NJ1 = 344;  // gemm1 jobs per step: 168 full (K=256) + 176 half (K=128)
constexpr int K1A = 2 * In;   // g_a1 row: [A0 | A1]
constexpr int K1W = 2 * In;   // g_w1 row: [W0 | W1s]
constexpr int K2W = 2 * Hn;   // g_w2 row: [W0 | W1s]

constexpr int TILE_W = 16384;  // 128x64 fp16 tile
constexpr int TILE_A = 8192;   // 64x64 fp16 tile
constexpr int STG1   = 2 * TILE_A + 2 * TILE_W;  // 48KB: A0,A1,W0,W1s
constexpr int SMEM_C = 2 * STG1;                 // 96KB (gemm2 path: 6x16KB = 96KB)

constexpr size_t P1SZ = (size_t)NS1 * Bn * Hn;   // 6 slots
constexpr size_t P2SZ = (size_t)S2 * Bn * On;

constexpr float VDEC = 0.5f;
constexpr float VTH  = 0.3f;
constexpr float GW   = 0.3f;

// ---------------- device scratch ----------------
__device__ __half g_a1[(size_t)Tn * Bn * K1A];  // [T][B][2048] 52.4MB
__device__ __half g_w1[(size_t)Hn * K1W];       // [H][2048] 16.8MB
__device__ __half g_w2[(size_t)On * K2W];       // [O][8192] 8.4MB
__device__ float    g_hv[Bn * Hn];
__device__ float    g_ov[Bn * On];
__device__ float    g_p1[2 * P1SZ];             // double-buffered by t&1 (24MB)
__device__ float    g_p2[2 * P2SZ];             // double-buffered by t&1
__device__ unsigned g_maxh[Tn];
__device__ unsigned g_maxo[Tn];
__device__ int      g_cc[Tn];                   // per-step gemm2 arrival counters

// ---------------- helpers ----------------
__device__ __forceinline__ unsigned enc_f(float x) {
    unsigned u = __float_as_uint(x);
    return (u & 0x80000000u) ? ~u : (u | 0x80000000u);
}
__device__ __forceinline__ float dec_f(unsigned k) {
    unsigned u = (k & 0x80000000u) ? (k & 0x7FFFFFFFu) : ~k;
    return __uint_as_float(u);
}
__device__ __forceinline__ float block_max256(float v) {
    #pragma unroll
    for (int o = 16; o > 0; o >>= 1)
        v = fmaxf(v, __shfl_xor_sync(0xffffffffu, v, o));
    __shared__ float red[8];
    int w = threadIdx.x >> 5;
    if ((threadIdx.x & 31) == 0) red[w] = v;
    __syncthreads();
    if (threadIdx.x == 0) {
        #pragma unroll
        for (int i = 1; i < 8; i++) v = fmaxf(v, red[i]);
    }
    return v;
}
__device__ __forceinline__ uint32_t smem_to_u32(const void* p) {
    uint32_t a;
    asm("{ .reg .u64 t; cvta.to.shared.u64 t, %1; cvt.u32.u64 %0, t; }" : "=r"(a) : "l"(p));
    return a;
}

#define LDSM_X4(r0, r1, r2, r3, addr) \
    asm volatile("ldmatrix.sync.aligned.m8n8.x4.shared.b16 {%0,%1,%2,%3}, [%4];" \
        : "=r"(r0), "=r"(r1), "=r"(r2), "=r"(r3) : "r"(addr))

#define MMA16816(d, a, b0, b1) \
    asm volatile("mma.sync.aligned.m16n8k16.row.col.f32.f16.f16.f32 " \
        "{%0,%1,%2,%3}, {%4,%5,%6,%7}, {%8,%9}, {%0,%1,%2,%3};" \
        : "+f"((d)[0]), "+f"((d)[1]), "+f"((d)[2]), "+f"((d)[3]) \
        : "r"((a)[0]), "r"((a)[1]), "r"((a)[2]), "r"((a)[3]), "r"(b0), "r"(b1))

#define HMUL2(o, x, y) asm("mul.f16x2 %0, %1, %2;" : "=r"(o) : "r"(x), "r"(y))

#define CP_ASYNC16(sdst, gsrc) \
    asm volatile("cp.async.cg.shared.global [%0], [%1], 16;" :: "r"(sdst), "l"(gsrc) : "memory")
#define CP_COMMIT() asm volatile("cp.async.commit_group;" ::: "memory")
#define CP_WAIT(n)  asm volatile("cp.async.wait_group %0;" :: "n"(n) : "memory")

// 128 rows x 64 fp16 tile (128B rows, SW128 swizzle)
__device__ __forceinline__ void cp_tile128(uint32_t sdst, const __half* __restrict__ src, int ld) {
    int tid = threadIdx.x;
    #pragma unroll
    for (int p = 0; p < 4; p++) {
        int id  = p * 256 + tid;
        int row = id >> 3, g = id & 7;
        uint32_t off = (uint32_t)(row * 128 + g * 16);
        off ^= (off >> 3) & 0x70u;
        CP_ASYNC16(sdst + off, src + (size_t)row * ld + g * 8);
    }
}
// 64 rows x 64 fp16 tile
__device__ __forceinline__ void cp_tile64(uint32_t sdst, const __half* __restrict__ src, int ld) {
    int tid = threadIdx.x;
    #pragma unroll
    for (int p = 0; p < 2; p++) {
        int id  = p * 256 + tid;
        int row = id >> 3, g = id & 7;
        uint32_t off = (uint32_t)(row * 128 + g * 16);
        off ^= (off >> 3) & 0x70u;
        CP_ASYNC16(sdst + off, src + (size_t)row * ld + g * 8);
    }
}

// ================= GEMM1 body: 64x128 output tile, variable K chunks =================
__device__ __forceinline__ void gemm1_body(int t, int mt, int nt, int kbase, int nchunks,
                                           int slot, uint32_t sbase) {
    const int tid  = threadIdx.x;
    const int wid  = tid >> 5, lane = tid & 31;
    const int wm   = wid & 1, wn = wid >> 1;      // 2m x 4n, warp tile 32x32
    const int m0   = mt * 64;
    const int n0   = nt * 128;

    const __half* Abase = g_a1 + (size_t)t * Bn * K1A + (size_t)m0 * K1A;

    auto issue = [&](int c) {
        if (c < nchunks) {
            uint32_t st = sbase + (uint32_t)(c & 1) * (uint32_t)STG1;
            int kk = kbase + c * 64;
            cp_tile64(st,              Abase + 0 * In + kk, K1A);
            cp_tile64(st + TILE_A,     Abase + 1 * In + kk, K1A);
            cp_tile128(st + 2 * TILE_A,          g_w1 + (size_t)n0 * K1W + 0 * In + kk, K1W);
            cp_tile128(st + 2 * TILE_A + TILE_W, g_w1 + (size_t)n0 * K1W + 1 * In + kk, K1W);
        }
        CP_COMMIT();
    };

    const int grp = lane >> 3, lrow = lane & 7;
    const int a_row = lrow + ((grp & 1) << 3);
    const uint32_t a_kb = (uint32_t)((grp >> 1) << 4);
    const int b_row = lrow + ((grp >> 1) << 3);
    const uint32_t b_kb = (uint32_t)((grp & 1) << 4);
    uint32_t aRB[2], aXR[2], bRB[2], bXR[2];
    #pragma unroll
    for (int mf = 0; mf < 2; mf++) {
        uint32_t rb = (uint32_t)((wm * 32 + mf * 16 + a_row) * 128);
        aRB[mf] = rb; aXR[mf] = (rb >> 3) & 0x70u;
    }
    #pragma unroll
    for (int pf = 0; pf < 2; pf++) {
        uint32_t rb = (uint32_t)((wn * 32 + pf * 16 + b_row) * 128);
        bRB[pf] = rb; bXR[pf] = (rb >> 3) & 0x70u;
    }

    float d[2][4][4] = {};
    issue(0);

    #pragma unroll 1
    for (int c = 0; c < nchunks; c++) {
        CP_WAIT(0);
        __syncthreads();
        issue(c + 1);
        const uint32_t st = sbase + (uint32_t)(c & 1) * (uint32_t)STG1;
        #pragma unroll
        for (int kk = 0; kk < 4; kk++) {
            const uint32_t ck = (uint32_t)(kk << 5);
            uint32_t b[2][4][2];
            #pragma unroll
            for (int j = 0; j < 2; j++) {
                #pragma unroll
                for (int pf = 0; pf < 2; pf++) {
                    uint32_t r0, r1, r2, r3;
                    LDSM_X4(r0, r1, r2, r3,
                            st + 2 * TILE_A + j * TILE_W + bRB[pf] + ((ck + b_kb) ^ bXR[pf]));
                    b[j][2 * pf][0] = r0; b[j][2 * pf][1] = r1;
                    b[j][2 * pf + 1][0] = r2; b[j][2 * pf + 1][1] = r3;
                }
            }
            uint32_t a0[2][4], a1[2][4], a2[2][4];
            #pragma unroll
            for (int mf = 0; mf < 2; mf++) {
                LDSM_X4(a0[mf][0], a0[mf][1], a0[mf][2], a0[mf][3],
                        st + aRB[mf] + ((ck + a_kb) ^ aXR[mf]));
                LDSM_X4(a1[mf][0], a1[mf][1], a1[mf][2], a1[mf][3],
                        st + TILE_A + aRB[mf] + ((ck + a_kb) ^ aXR[mf]));
                #pragma unroll
                for (int r = 0; r < 4; r++) HMUL2(a2[mf][r], a0[mf][r], 0x14001400u);
            }
            #pragma unroll
            for (int mf = 0; mf < 2; mf++)
                #pragma unroll
                for (int nf = 0; nf < 4; nf++) {
                    MMA16816(d[mf][nf], a0[mf], b[0][nf][0], b[0][nf][1]);
                    MMA16816(d[mf][nf], a1[mf], b[0][nf][0], b[0][nf][1]);
                    MMA16816(d[mf][nf], a2[mf], b[1][nf][0], b[1][nf][1]);
                }
        }
        __syncthreads();
    }

    float* P = g_p1 + (size_t)(t & 1) * P1SZ + (size_t)slot * Bn * Hn + n0;
    const int r0 = lane >> 2, c0 = (lane & 3) * 2;
    #pragma unroll
    for (int mf = 0; mf < 2; mf++) {
        #pragma unroll
        for (int nf = 0; nf < 4; nf++) {
            int m = m0 + wm * 32 + mf * 16 + r0;
            int n = wn * 32 + nf * 8 + c0;
            *reinterpret_cast<float2*>(&P[(size_t)m * Hn + n]) =
                make_float2(d[mf][nf][0], d[mf][nf][1]);
            *reinterpret_cast<float2*>(&P[(size_t)(m + 8) * Hn + n]) =
                make_float2(d[mf][nf][2], d[mf][nf][3]);
        }
    }
}

// g in [0, 344): jobs 0..167 full K=256 tiles (ids 0..167); 168..343 half K=128 tiles.
// id -> (mt = id&1, nt = (id>>1)&31, z = id>>6). Full: slot=z (0,1,2), kbase=z*256, 4 chunks.
// Half j: id = 168 + (j>>1), half = j&1; zz = id>>6 (2 or 3);
//   slot = (zz==2 ? 2 : 4) + half, kbase = zz*256 + half*128, 2 chunks.
__device__ __forceinline__ void gemm1_dispatch(int t, int g, uint32_t sbase) {
    if (g < 168) {
        int mt = g & 1, nt = (g >> 1) & 31, z = g >> 6;
        gemm1_body(t, mt, nt, z * 256, 4, z, sbase);
    } else {
        int j = g - 168;
        int id = 168 + (j >> 1), half = j & 1;
        int mt = id & 1, nt = (id >> 1) & 31, zz = id >> 6;
        int slot = ((zz == 2) ? 2 : 4) + half;
        gemm1_body(t, mt, nt, zz * 256 + half * 128, 2, slot, sbase);
    }
}

// ================= GEMM2 + fuse1(t) pre-sync; fuse2(t-1) post-epilogue =================
__device__ __forceinline__ void gemm2_fused(float* __restrict__ out, int t, int bid, uint32_t sbase) {
    const int tid  = threadIdx.x;
    const int wid  = tid >> 5, lane = tid & 31;
    const int wm   = wid & 1, wn = wid >> 1;      // 2m x 4n, warp tile 64x32
    const int nt   = bid >> 5, z = bid & 31;
    const int n0   = nt * 128;
    const int kbase = z * 128;

    // W loads first (overlap with fuse phase)
    #pragma unroll
    for (int c = 0; c < NB2; c++)
        #pragma unroll
        for (int seg = 0; seg < 2; seg++)
            cp_tile128(sbase + (c * 2 + seg) * TILE_W,
                       g_w2 + (size_t)n0 * K2W + seg * Hn + kbase + c * 64, K2W);
    CP_COMMIT();

    // ---- fuse1(t): this CTA updates hv row `bid` (1024 float4); sums 6 slots ----
    {
        const bool  hp   = (t > 0);
        const float thrp = hp ? VTH * tanhf(GW * dec_f(g_maxh[t - 1])) : 0.f;
        constexpr int NF4 = Bn * Hn / 4;
        const float4* p14 = reinterpret_cast<const float4*>(g_p1 + (size_t)(t & 1) * P1SZ);
        float4* hv4 = reinterpret_cast<float4*>(g_hv);
        float lmax = -3.4e38f;
        #pragma unroll
        for (int q = 0; q < 4; q++) {
            int fi = bid * 1024 + q * 256 + tid;
            float4 s = p14[fi];
            #pragma unroll
            for (int zz = 1; zz < NS1; zz++) {
                float4 p = p14[(size_t)zz * NF4 + fi];
                s.x += p.x; s.y += p.y; s.z += p.z; s.w += p.w;
            }
            float4 ho = hp ? hv4[fi] : make_float4(0.f, 0.f, 0.f, 0.f);
            float4 hn;
            hn.x = ho.x * ((hp && ho.x > thrp) ? 0.f : VDEC) + s.x;
            hn.y = ho.y * ((hp && ho.y > thrp) ? 0.f : VDEC) + s.y;
            hn.z = ho.z * ((hp && ho.z > thrp) ? 0.f : VDEC) + s.z;
            hn.w = ho.w * ((hp && ho.w > thrp) ? 0.f : VDEC) + s.w;
            hv4[fi] = hn;
            lmax = fmaxf(lmax, fmaxf(fmaxf(hn.x, hn.y), fmaxf(hn.z, hn.w)));
        }
        float bm = block_max256(lmax);
        if (tid == 0) atomicMax(&g_maxh[t], enc_f(bm));
    }

    // ---- device-wide sync across the 128 gemm2 CTAs (all wave-1 resident) ----
    __threadfence();
    __syncthreads();
    if (tid == 0) {
        atomicAdd(&g_cc[t], 1);
        while (((volatile int*)g_cc)[t] < 128) __nanosleep(64);
    }
    __syncthreads();

    const float thr = VTH * tanhf(GW * dec_f(*((volatile unsigned*)&g_maxh[t])));
    CP_WAIT(0);
    __syncthreads();

    const int grp = lane >> 3, lrow = lane & 7;
    const int a_row = lrow + ((grp & 1) << 3);
    const uint32_t a_kb = (uint32_t)((grp >> 1) << 4);
    const int b_row = lrow + ((grp >> 1) << 3);
    const uint32_t b_kb = (uint32_t)((grp & 1) << 4);
    uint32_t aRB[4], aXR[4], bRB[2], bXR[2];
    #pragma unroll
    for (int mf = 0; mf < 4; mf++) {
        uint32_t rb = (uint32_t)((wm * 64 + mf * 16 + a_row) * 128);
        aRB[mf] = rb; aXR[mf] = (rb >> 3) & 0x70u;
    }
    #pragma unroll
    for (int pf = 0; pf < 2; pf++) {
        uint32_t rb = (uint32_t)((wn * 32 + pf * 16 + b_row) * 128);
        bRB[pf] = rb; bXR[pf] = (rb >> 3) & 0x70u;
    }

    float d[4][4][4] = {};
    #pragma unroll 1
    for (int c = 0; c < NB2; c++) {
        const uint32_t ta  = sbase + 4 * TILE_W;
        const uint32_t tas = sbase + 5 * TILE_W;
        #pragma unroll
        for (int p = 0; p < 4; p++) {
            int id = p * 256 + tid;
            int row = id >> 3, g = id & 7;
            const float4* sp = reinterpret_cast<const float4*>(
                g_hv + (size_t)row * Hn + kbase + c * 64 + g * 8);
            float4 va = __ldcg(sp), vb = __ldcg(sp + 1);
            uint32_t m0 = (va.x > thr ? 0x0001u : 0u) | (va.y > thr ? 0x00010000u : 0u);
            uint32_t m1 = (va.z > thr ? 0x0001u : 0u) | (va.w > thr ? 0x00010000u : 0u);
            uint32_t m2 = (vb.x > thr ? 0x0001u : 0u) | (vb.y > thr ? 0x00010000u : 0u);
            uint32_t m3 = (vb.z > thr ? 0x0001u : 0u) | (vb.w > thr ? 0x00010000u : 0u);
            uint32_t off = (uint32_t)(row * 128 + g * 16);
            off ^= (off >> 3) & 0x70u;
            asm volatile("st.shared.v4.b32 [%0], {%1,%2,%3,%4};"
                :: "r"(ta + off), "r"(m0 * 0x3C00u), "r"(m1 * 0x3C00u),
                   "r"(m2 * 0x3C00u), "r"(m3 * 0x3C00u) : "memory");
            asm volatile("st.shared.v4.b32 [%0], {%1,%2,%3,%4};"
                :: "r"(tas + off), "r"(m0 * 0x1400u), "r"(m1 * 0x1400u),
                   "r"(m2 * 0x1400u), "r"(m3 * 0x1400u) : "memory");
        }
        __syncthreads();
        #pragma unroll
        for (int kk = 0; kk < 4; kk++) {
            const uint32_t ck = (uint32_t)(kk << 5);
            #pragma unroll
            for (int p = 0; p < 2; p++) {  // (S,W0c), (Ss,W1c)
                uint32_t a[4][4];
                #pragma unroll
                for (int mf = 0; mf < 4; mf++)
                    LDSM_X4(a[mf][0], a[mf][1], a[mf][2], a[mf][3],
                            sbase + (4 + p) * TILE_W + aRB[mf] + ((ck + a_kb) ^ aXR[mf]));
                uint32_t b[4][2];
                #pragma unroll
                for (int pf = 0; pf < 2; pf++) {
                    uint32_t r0, r1, r2, r3;
                    LDSM_X4(r0, r1, r2, r3,
                            sbase + (c * 2 + p) * TILE_W + bRB[pf] + ((ck + b_kb) ^ bXR[pf]));
                    b[2 * pf][0] = r0; b[2 * pf][1] = r1;
                    b[2 * pf + 1][0] = r2; b[2 * pf + 1][1] = r3;
                }
                #pragma unroll
                for (int mf = 0; mf < 4; mf++)
                    #pragma unroll
                    for (int nf = 0; nf < 4; nf++)
                        MMA16816(d[mf][nf], a[mf], b[nf][0], b[nf][1]);
            }
        }
        __syncthreads();
    }

    float* P = g_p2 + (size_t)(t & 1) * P2SZ + (size_t)z * Bn * On + n0;
    const int r0 = lane >> 2, c0 = (lane & 3) * 2;
    #pragma unroll
    for (int mf = 0; mf < 4; mf++) {
        #pragma unroll
        for (int nf = 0; nf < 4; nf++) {
            int m = wm * 64 + mf * 16 + r0;
            int n = wn * 32 + nf * 8 + c0;
            *reinterpret_cast<float2*>(&P[(size_t)m * On + n]) =
                make_float2(d[mf][nf][0], d[mf][nf][1]);
            *reinterpret_cast<float2*>(&P[(size_t)(m + 8) * On + n]) =
                make_float2(d[mf][nf][2], d[mf][nf][3]);
        }
    }

    // ---- fuse2(t-1) AFTER the epilogue (off the pre-sync critical path) ----
    if (t > 0 && bid < 64) {
        __syncthreads();
        const int pt = t - 1;
        const bool  hp   = (pt > 0);
        const float thrp = hp ? VTH * tanhf(GW * dec_f(g_maxo[pt - 1])) : 0.f;
        constexpr int NF4 = Bn * On / 4;
        const int fi = bid * 256 + tid;
        const float4* p24 = reinterpret_cast<const float4*>(g_p2 + (size_t)(pt & 1) * P2SZ);
        float4* ov4 = reinterpret_cast<float4*>(g_ov);
        float4* o4  = reinterpret_cast<float4*>(out);
        float4 s = p24[fi];
        #pragma unroll
        for (int zz = 1; zz < S2; zz++) {
            float4 p = p24[(size_t)zz * NF4 + fi];
            s.x += p.x; s.y += p.y; s.z += p.z; s.w += p.w;
        }
        float4 oo = hp ? ov4[fi] : make_float4(0.f, 0.f, 0.f, 0.f);
        float4 os;
        os.x = (hp && oo.x > thrp) ? 1.f : 0.f;
        os.y = (hp && oo.y > thrp) ? 1.f : 0.f;
        os.z = (hp && oo.z > thrp) ? 1.f : 0.f;
        os.w = (hp && oo.w > thrp) ? 1.f : 0.f;
        float4 acc = hp ? o4[fi] : make_float4(0.f, 0.f, 0.f, 0.f);
        acc.x += os.x; acc.y += os.y; acc.z += os.z; acc.w += os.w;
        o4[fi] = acc;
        float4 nv;
        nv.x = oo.x * ((os.x > 0.f) ? 0.f : VDEC) + s.x;
        nv.y = oo.y * ((os.y > 0.f) ? 0.f : VDEC) + s.y;
        nv.z = oo.z * ((os.z > 0.f) ? 0.f : VDEC) + s.z;
        nv.w = oo.w * ((os.w > 0.f) ? 0.f : VDEC) + s.w;
        ov4[fi] = nv;
        float lmax = fmaxf(fmaxf(nv.x, nv.y), fmaxf(nv.z, nv.w));
        float bm = block_max256(lmax);
        if (tid == 0) atomicMax(&g_maxo[pt], enc_f(bm));
    }
}

// ---------------- kernels ----------------
__global__ void __launch_bounds__(256, 2) gemm1_k(int t) {
    extern __shared__ char smem[];
    gemm1_dispatch(t, blockIdx.x, smem_to_u32(smem));
}
__global__ void __launch_bounds__(256, 2) combo_k(float* __restrict__ out, int t) {
    extern __shared__ char smem[];
    const uint32_t sbase = smem_to_u32(smem);
    if (blockIdx.x < 128) {
        gemm2_fused(out, t, blockIdx.x, sbase);
    } else if (t + 1 < Tn) {
        gemm1_dispatch(t + 1, blockIdx.x - 128, sbase);
    }
}

// ---------------- prep kernels ----------------
__global__ void reset_k() {
    int i = threadIdx.x;
    if (i < Tn) { g_maxh[i] = 0x007FFFFFu; g_maxo[i] = 0x007FFFFFu; g_cc[i] = 0; }
}

// zero p1 slot 3, cols 0..2559, both buffers (sub-blocks whose z2 is a full tile)
__global__ void zero3_k() {
    int idx = blockIdx.x * 256 + threadIdx.x;          // 163840 float4 total
    int buf = idx >= 81920;
    int rem = idx - buf * 81920;
    int row = rem / 640, col4 = rem % 640;
    reinterpret_cast<float4*>(g_p1)[ (size_t)buf * (P1SZ / 4)
        + (size_t)3 * Bn * Hn / 4 + (size_t)row * (Hn / 4) + col4 ] =
        make_float4(0.f, 0.f, 0.f, 0.f);
}

__device__ __forceinline__ void split2(float v, __half& s0, __half& s1) {
    s0 = __float2half_rn(v);
    s1 = __float2half_rn(v - __half2float(s0));
}
__device__ __forceinline__ void split_w(float v, __half& w0, __half& w1s) {
    w0 = __float2half_rn(v);
    w1s = __float2half_rn((v - __half2float(w0)) * 1024.0f);
}

// spike_data [B][I][T] fp32 -> g_a1 [T][B][ A0 | A1 ]
__global__ void prep_a1_k(const float* __restrict__ sd) {
    __shared__ float tile[32][33];
    int b = blockIdx.z, i0 = blockIdx.y * 32, t0 = blockIdx.x * 32;
    int tx = threadIdx.x, ty = threadIdx.y;
    #pragma unroll
    for (int j = 0; j < 32; j += 8) {
        int i = i0 + ty + j, tt = t0 + tx;
        tile[ty + j][tx] = (tt < Tn) ? sd[((size_t)b * In + i) * Tn + tt] : 0.f;
    }
    __syncthreads();
    #pragma unroll
    for (int j = 0; j < 32; j += 8) {
        int tt = t0 + ty + j, i = i0 + tx;
        if (tt < Tn) {
            __half a0, a1;
            split2(tile[tx][ty + j], a0, a1);
            size_t base = ((size_t)tt * Bn + b) * K1A;
            g_a1[base + 0 * In + i] = a0;
            g_a1[base + 1 * In + i] = a1;
        }
    }
}

__global__ void conv_w1_k(const float* __restrict__ w) {
    int idx = blockIdx.x * 256 + threadIdx.x;  // exact Hn*In
    __half w0, w1s;
    split_w(w[idx], w0, w1s);
    int h = idx >> 10, k = idx & 1023;
    size_t base = (size_t)h * K1W;
    g_w1[base + 0 * In + k] = w0;
    g_w1[base + 1 * In + k] = w1s;
}
__global__ void conv_w2_k(const float* __restrict__ w) {
    int idx = blockIdx.x * 256 + threadIdx.x;  // exact On*Hn
    __half w0, w1s;
    split_w(w[idx], w0, w1s);
    int o = idx >> 12, k = idx & 4095;
    size_t base = (size_t)o * K2W;
    g_w2[base + 0 * Hn + k] = w0;
    g_w2[base + 1 * Hn + k] = w1s;
}

// ---------------- standalone fuse2 (t=99) + final ----------------
__global__ __launch_bounds__(256) void fuse2_k(float* __restrict__ out, int t) {
    const bool  hp   = (t > 0);
    const float thrp = hp ? VTH * tanhf(GW * dec_f(g_maxo[t - 1])) : 0.f;
    constexpr int NF4 = Bn * On / 4;
    int fi = blockIdx.x * 256 + threadIdx.x;
    const float4* p24 = reinterpret_cast<const float4*>(g_p2 + (size_t)(t & 1) * P2SZ);
    float4* ov4 = reinterpret_cast<float4*>(g_ov);
    float4* o4  = reinterpret_cast<float4*>(out);
    float4 s = p24[fi];
    #pragma unroll
    for (int zz = 1; zz < S2; zz++) {
        float4 p = p24[(size_t)zz * NF4 + fi];
        s.x += p.x; s.y += p.y; s.z += p.z; s.w += p.w;
    }
    float4 oo = hp ? ov4[fi] : make_float4(0.f, 0.f, 0.f, 0.f);
    float4 os;
    os.x = (hp && oo.x > thrp) ? 1.f : 0.f;
    os.y = (hp && oo.y > thrp) ? 1.f : 0.f;
    os.z = (hp && oo.z > thrp) ? 1.f : 0.f;
    os.w = (hp && oo.w > thrp) ? 1.f : 0.f;
    float4 acc = hp ? o4[fi] : make_float4(0.f, 0.f, 0.f, 0.f);
    acc.x += os.x; acc.y += os.y; acc.z += os.z; acc.w += os.w;
    o4[fi] = acc;
    float4 nv;
    nv.x = oo.x * ((os.x > 0.f) ? 0.f : VDEC) + s.x;
    nv.y = oo.y * ((os.y > 0.f) ? 0.f : VDEC) + s.y;
    nv.z = oo.z * ((os.z > 0.f) ? 0.f : VDEC) + s.z;
    nv.w = oo.w * ((os.w > 0.f) ? 0.f : VDEC) + s.w;
    ov4[fi] = nv;
    float lmax = fmaxf(fmaxf(nv.x, nv.y), fmaxf(nv.z, nv.w));
    float bm = block_max256(lmax);
    if (threadIdx.x == 0) atomicMax(&g_maxo[t], enc_f(bm));
}

__global__ __launch_bounds__(256) void final_k(float* __restrict__ out) {
    const float thr = VTH * tanhf(GW * dec_f(g_maxo[Tn - 1]));
    int fi = blockIdx.x * 256 + threadIdx.x;
    float4 ov = reinterpret_cast<const float4*>(g_ov)[fi];
    float4 o  = reinterpret_cast<float4*>(out)[fi];
    o.x += (ov.x > thr) ? 1.f : 0.f;
    o.y += (ov.y > thr) ? 1.f : 0.f;
    o.z += (ov.z > thr) ? 1.f : 0.f;
    o.w += (ov.w > thr) ? 1.f : 0.f;
    reinterpret_cast<float4*>(out)[fi] = o;
}

// ---------------- launch ----------------
extern "C" void kernel_launch(void* const* d_in, const int* in_sizes, int n_in,
                              void* d_out, int out_size) {
    const float* sd    = (const float*)d_in[0];  // spike_data [B][I][T]
    const float* w_hid = (const float*)d_in[5];  // [H][I]
    const float* w_out = (const float*)d_in[6];  // [O][H]
    float* out = (float*)d_out;                  // [B][O]

    cudaFuncSetAttribute((const void*)gemm1_k, cudaFuncAttributeMaxDynamicSharedMemorySize, SMEM_C);
    cudaFuncSetAttribute((const void*)combo_k, cudaFuncAttributeMaxDynamicSharedMemorySize, SMEM_C);

    reset_k<<<1, 128>>>();
    zero3_k<<<640, 256>>>();
    prep_a1_k<<<dim3((Tn + 31) / 32, In / 32, Bn), dim3(32, 8)>>>(sd);
    conv_w1_k<<<Hn * In / 256, 256>>>(w_hid);
    conv_w2_k<<<On * Hn / 256, 256>>>(w_out);

    gemm1_k<<<NJ1, 256, SMEM_C>>>(0);
    for (int t = 0; t < Tn; t++)
        combo_k<<<128 + NJ1, 256, SMEM_C>>>(out, t);
    fuse2_k<<<64, 256>>>(out, Tn - 1);
    final_k<<<64, 256>>>(out);
}